// round 1
// baseline (speedup 1.0000x reference)
#include <cuda_runtime.h>
#include <cuda_bf16.h>

#define NMAX   100000
#define EMAX   1600000
#define CIN_   128
#define COUT_  64

// Scratch (device globals — no allocation allowed)
__device__ float g_H[NMAX * COUT_];
__device__ float g_agg[NMAX * COUT_];
__device__ float g_dinv[NMAX];
__device__ int   g_deg[NMAX];

// ---------------------------------------------------------------------------
// 0) zero agg + deg
// ---------------------------------------------------------------------------
__global__ void zero_kernel(int n_agg, int n_nodes) {
    int i = blockIdx.x * blockDim.x + threadIdx.x;
    int stride = gridDim.x * blockDim.x;
    for (int j = i; j < n_agg; j += stride)   g_agg[j] = 0.0f;
    for (int j = i; j < n_nodes; j += stride) g_deg[j] = 0;
}

// ---------------------------------------------------------------------------
// 1) degree count over dst
// ---------------------------------------------------------------------------
__global__ void deg_kernel(const int* __restrict__ dst, int E) {
    int i = blockIdx.x * blockDim.x + threadIdx.x;
    if (i < E) atomicAdd(&g_deg[dst[i]], 1);
}

// ---------------------------------------------------------------------------
// 2) dinv_sqrt = rsqrt(1 + deg)
// ---------------------------------------------------------------------------
__global__ void dinv_kernel(int n) {
    int i = blockIdx.x * blockDim.x + threadIdx.x;
    if (i < n) g_dinv[i] = rsqrtf(1.0f + (float)g_deg[i]);
}

// ---------------------------------------------------------------------------
// 3) GEMM: H = X @ W + b     (N x 128) @ (128 x 64)
//    tile 128 rows x 64 cols, 256 threads, 8x4 register blocking
// ---------------------------------------------------------------------------
__global__ __launch_bounds__(256) void gemm_kernel(
    const float* __restrict__ X, const float* __restrict__ W,
    const float* __restrict__ bias, int n)
{
    __shared__ float Xs[16][132];   // [k][row], padded (stride 132 keeps 16B align)
    __shared__ float Ws[16][64];    // [k][col]

    const int tid  = threadIdx.x;
    const int tcol = tid & 15;      // col group: cols tcol*4 .. +3
    const int trow = tid >> 4;      // row group: rows trow*8 .. +7
    const int row0 = blockIdx.x * 128;

    float acc[8][4];
    #pragma unroll
    for (int r = 0; r < 8; r++)
        #pragma unroll
        for (int c = 0; c < 4; c++) acc[r][c] = 0.0f;

    for (int k0 = 0; k0 < CIN_; k0 += 16) {
        // load X tile (128 rows x 16 k), transposed into Xs[k][row]
        #pragma unroll
        for (int p = 0; p < 2; p++) {
            int r  = p * 64 + (tid >> 2);
            int kq = tid & 3;
            int rr = row0 + r;
            const float* xp = X + (long)(rr < n ? rr : 0) * CIN_ + k0 + kq * 4;
            float4 v = *(const float4*)xp;
            Xs[kq * 4 + 0][r] = v.x;
            Xs[kq * 4 + 1][r] = v.y;
            Xs[kq * 4 + 2][r] = v.z;
            Xs[kq * 4 + 3][r] = v.w;
        }
        // load W tile (16 k x 64 cols)
        {
            int k    = tid >> 4;
            int colq = tid & 15;
            float4 v = *(const float4*)(W + (long)(k0 + k) * COUT_ + colq * 4);
            *(float4*)&Ws[k][colq * 4] = v;
        }
        __syncthreads();

        #pragma unroll
        for (int kk = 0; kk < 16; kk++) {
            float a[8], b[4];
            *(float4*)&a[0] = *(const float4*)&Xs[kk][trow * 8];
            *(float4*)&a[4] = *(const float4*)&Xs[kk][trow * 8 + 4];
            *(float4*)&b[0] = *(const float4*)&Ws[kk][tcol * 4];
            #pragma unroll
            for (int r = 0; r < 8; r++)
                #pragma unroll
                for (int c = 0; c < 4; c++)
                    acc[r][c] = fmaf(a[r], b[c], acc[r][c]);
        }
        __syncthreads();
    }

    float4 bb = *(const float4*)(bias + tcol * 4);
    #pragma unroll
    for (int r = 0; r < 8; r++) {
        int row = row0 + trow * 8 + r;
        if (row < n) {
            float4 o;
            o.x = acc[r][0] + bb.x;
            o.y = acc[r][1] + bb.y;
            o.z = acc[r][2] + bb.z;
            o.w = acc[r][3] + bb.w;
            *(float4*)&g_H[(long)row * COUT_ + tcol * 4] = o;
        }
    }
}

// ---------------------------------------------------------------------------
// 4) edge scatter: agg[dst] += dinv[src]*dinv[dst] * H[src]
//    16 threads per edge, each does one float4 + red.global.add.v4.f32
// ---------------------------------------------------------------------------
__global__ __launch_bounds__(256) void edge_kernel(
    const int* __restrict__ src, const int* __restrict__ dst, int E)
{
    long t = (long)blockIdx.x * blockDim.x + threadIdx.x;
    long e = t >> 4;
    if (e >= E) return;
    int c = ((int)t & 15) * 4;

    int s = __ldg(&src[e]);
    int d = __ldg(&dst[e]);
    float coef = g_dinv[s] * g_dinv[d];

    float4 h = *(const float4*)&g_H[(long)s * COUT_ + c];
    float* p = &g_agg[(long)d * COUT_ + c];
    asm volatile("red.global.add.v4.f32 [%0], {%1, %2, %3, %4};"
                 :: "l"(p), "f"(h.x * coef), "f"(h.y * coef),
                    "f"(h.z * coef), "f"(h.w * coef)
                 : "memory");
}

// ---------------------------------------------------------------------------
// 5) finalize: out = relu(agg + H * dinv^2)
// ---------------------------------------------------------------------------
__global__ __launch_bounds__(256) void final_kernel(float* __restrict__ out, int n) {
    long t = (long)blockIdx.x * blockDim.x + threadIdx.x;
    if (t >= (long)n * 16) return;
    int node = (int)(t >> 4);
    int c    = ((int)t & 15) * 4;

    float di   = g_dinv[node];
    float self = di * di;
    long  off  = (long)node * COUT_ + c;
    float4 a = *(const float4*)&g_agg[off];
    float4 h = *(const float4*)&g_H[off];
    float4 o;
    o.x = fmaxf(fmaf(h.x, self, a.x), 0.0f);
    o.y = fmaxf(fmaf(h.y, self, a.y), 0.0f);
    o.z = fmaxf(fmaf(h.z, self, a.z), 0.0f);
    o.w = fmaxf(fmaf(h.w, self, a.w), 0.0f);
    *(float4*)&out[off] = o;
}

// ---------------------------------------------------------------------------
extern "C" void kernel_launch(void* const* d_in, const int* in_sizes, int n_in,
                              void* d_out, int out_size)
{
    const float* X    = (const float*)d_in[0];   // (N, 128)
    const float* W    = (const float*)d_in[1];   // (128, 64)
    const float* bias = (const float*)d_in[2];   // (64,)
    const int*   src  = (const int*)d_in[3];     // (E,)
    const int*   dst  = (const int*)d_in[4];     // (E,)
    float*       out  = (float*)d_out;           // (N, 64)

    const int n = in_sizes[0] / CIN_;
    const int E = in_sizes[3];

    // 0) zero scratch
    zero_kernel<<<1024, 256>>>(n * COUT_, n);
    // 1) degrees
    deg_kernel<<<(E + 255) / 256, 256>>>(dst, E);
    // 2) dinv_sqrt
    dinv_kernel<<<(n + 255) / 256, 256>>>(n);
    // 3) H = X @ W + b  (can overlap with 1/2 logically, but stream-ordered is fine)
    gemm_kernel<<<(n + 127) / 128, 256>>>(X, W, bias, n);
    // 4) edge scatter-add
    {
        long threads = (long)E * 16;
        int blocks = (int)((threads + 255) / 256);
        edge_kernel<<<blocks, 256>>>(src, dst, E);
    }
    // 5) finalize
    {
        long threads = (long)n * 16;
        int blocks = (int)((threads + 255) / 256);
        final_kernel<<<blocks, 256>>>(out, n);
    }
}

// round 2
// speedup vs baseline: 1.1675x; 1.1675x over previous
#include <cuda_runtime.h>
#include <cuda_bf16.h>

#define NMAX   100000
#define EMAX   1600000
#define CIN_   128
#define COUT_  64
#define SCAN_C 1024
#define NBLK_MAX 128

// Scratch (device globals — no allocation allowed)
__device__ float g_H[NMAX * COUT_];
__device__ float g_dinv[NMAX];
__device__ int   g_deg[NMAX];
__device__ int   g_rowoff[NMAX];
__device__ int   g_cursor[NMAX];
__device__ int2  g_edge[EMAX];      // {src, bitcast(dinv[src])}
__device__ int   g_bsum[NBLK_MAX];
__device__ int   g_boff[NBLK_MAX];

// ---------------------------------------------------------------------------
// 0) zero deg
// ---------------------------------------------------------------------------
__global__ void zero_kernel(int n) {
    int i = blockIdx.x * blockDim.x + threadIdx.x;
    if (i < n) g_deg[i] = 0;
}

// ---------------------------------------------------------------------------
// 1) degree count over dst
// ---------------------------------------------------------------------------
__global__ void deg_kernel(const int* __restrict__ dst, int E) {
    int i = blockIdx.x * blockDim.x + threadIdx.x;
    if (i < E) atomicAdd(&g_deg[dst[i]], 1);
}

// ---------------------------------------------------------------------------
// 2) scan stage 1: per-block exclusive scan of deg (1024 items/block),
//    also computes dinv = rsqrt(1+deg)
// ---------------------------------------------------------------------------
__global__ __launch_bounds__(256) void scan1_kernel(int n) {
    __shared__ int wsum[8];
    const int b    = blockIdx.x;
    const int base = b * SCAN_C + threadIdx.x * 4;
    const int lane = threadIdx.x & 31;
    const int warp = threadIdx.x >> 5;

    int v[4];
    #pragma unroll
    for (int i = 0; i < 4; i++) {
        int idx = base + i;
        v[i] = (idx < n) ? g_deg[idx] : 0;
        if (idx < n) g_dinv[idx] = rsqrtf(1.0f + (float)v[i]);
    }
    int tsum = v[0] + v[1] + v[2] + v[3];

    // warp inclusive scan of per-thread sums
    int x = tsum;
    #pragma unroll
    for (int off = 1; off < 32; off <<= 1) {
        int y = __shfl_up_sync(0xFFFFFFFFu, x, off);
        if (lane >= off) x += y;
    }
    if (lane == 31) wsum[warp] = x;
    __syncthreads();
    if (threadIdx.x == 0) {
        int run = 0;
        #pragma unroll
        for (int w = 0; w < 8; w++) { int t = wsum[w]; wsum[w] = run; run += t; }
        g_bsum[b] = run;
    }
    __syncthreads();

    int excl = wsum[warp] + x - tsum;   // exclusive prefix for this thread's item 0
    int run = excl;
    #pragma unroll
    for (int i = 0; i < 4; i++) {
        int idx = base + i;
        if (idx < n) g_rowoff[idx] = run;
        run += v[i];
    }
}

// ---------------------------------------------------------------------------
// 3) scan stage 2: exclusive scan of block sums (single block, <=128 blocks)
// ---------------------------------------------------------------------------
__global__ __launch_bounds__(128) void scan2_kernel(int nblk) {
    __shared__ int ws[4];
    int i = threadIdx.x;
    int v = (i < nblk) ? g_bsum[i] : 0;
    int lane = i & 31, w = i >> 5;
    int x = v;
    #pragma unroll
    for (int off = 1; off < 32; off <<= 1) {
        int y = __shfl_up_sync(0xFFFFFFFFu, x, off);
        if (lane >= off) x += y;
    }
    if (lane == 31) ws[w] = x;
    __syncthreads();
    if (i == 0) {
        int run = 0;
        #pragma unroll
        for (int j = 0; j < 4; j++) { int t = ws[j]; ws[j] = run; run += t; }
    }
    __syncthreads();
    if (i < nblk) g_boff[i] = ws[w] + x - v;
}

// ---------------------------------------------------------------------------
// 4) scan stage 3: add block offsets, init cursor = rowoff
// ---------------------------------------------------------------------------
__global__ void scan3_kernel(int n) {
    int i = blockIdx.x * blockDim.x + threadIdx.x;
    if (i < n) {
        int r = g_rowoff[i] + g_boff[i / SCAN_C];
        g_rowoff[i] = r;
        g_cursor[i] = r;
    }
}

// ---------------------------------------------------------------------------
// 5) CSR fill: slot edges by dst; pack {src, dinv[src]}
// ---------------------------------------------------------------------------
__global__ void fill_kernel(const int* __restrict__ src,
                            const int* __restrict__ dst, int E) {
    int i = blockIdx.x * blockDim.x + threadIdx.x;
    if (i >= E) return;
    int s = src[i];
    int d = dst[i];
    int pos = atomicAdd(&g_cursor[d], 1);
    g_edge[pos] = make_int2(s, __float_as_int(g_dinv[s]));
}

// ---------------------------------------------------------------------------
// 6) GEMM: H = X @ W + b  — packed f32x2 FMA (2 FMA lanes / issue)
//    tile 128 rows x 64 cols, 256 threads, 8x4 register blocking
// ---------------------------------------------------------------------------
#define FMA2(d, a, b) asm("fma.rn.f32x2 %0, %1, %2, %3;" \
                          : "=l"(d) : "l"(a), "l"(b), "l"(d))

__global__ __launch_bounds__(256) void gemm_kernel(
    const float* __restrict__ X, const float* __restrict__ W,
    const float* __restrict__ bias, int n)
{
    __shared__ float2 Xs2[16][130];   // duplicated (x,x) pairs; stride keeps 16B align
    __shared__ float  Ws[16][64];

    const int tid  = threadIdx.x;
    const int tcol = tid & 15;        // cols tcol*4 .. +3
    const int trow = tid >> 4;        // rows trow*8 .. +7
    const int row0 = blockIdx.x * 128;

    unsigned long long acc[8][2];
    #pragma unroll
    for (int r = 0; r < 8; r++) { acc[r][0] = 0ull; acc[r][1] = 0ull; }

    for (int k0 = 0; k0 < CIN_; k0 += 16) {
        #pragma unroll
        for (int p = 0; p < 2; p++) {
            int r  = p * 64 + (tid >> 2);
            int kq = tid & 3;
            int rr = row0 + r;
            const float* xp = X + (long)(rr < n ? rr : 0) * CIN_ + k0 + kq * 4;
            float4 v = *(const float4*)xp;
            Xs2[kq * 4 + 0][r] = make_float2(v.x, v.x);
            Xs2[kq * 4 + 1][r] = make_float2(v.y, v.y);
            Xs2[kq * 4 + 2][r] = make_float2(v.z, v.z);
            Xs2[kq * 4 + 3][r] = make_float2(v.w, v.w);
        }
        {
            int k    = tid >> 4;
            int colq = tid & 15;
            float4 v = *(const float4*)(W + (long)(k0 + k) * COUT_ + colq * 4);
            *(float4*)&Ws[k][colq * 4] = v;
        }
        __syncthreads();

        #pragma unroll
        for (int kk = 0; kk < 16; kk++) {
            ulonglong2 a01 = *(const ulonglong2*)&Xs2[kk][trow * 8 + 0];
            ulonglong2 a23 = *(const ulonglong2*)&Xs2[kk][trow * 8 + 2];
            ulonglong2 a45 = *(const ulonglong2*)&Xs2[kk][trow * 8 + 4];
            ulonglong2 a67 = *(const ulonglong2*)&Xs2[kk][trow * 8 + 6];
            ulonglong2 b   = *(const ulonglong2*)&Ws[kk][tcol * 4];
            FMA2(acc[0][0], a01.x, b.x);  FMA2(acc[0][1], a01.x, b.y);
            FMA2(acc[1][0], a01.y, b.x);  FMA2(acc[1][1], a01.y, b.y);
            FMA2(acc[2][0], a23.x, b.x);  FMA2(acc[2][1], a23.x, b.y);
            FMA2(acc[3][0], a23.y, b.x);  FMA2(acc[3][1], a23.y, b.y);
            FMA2(acc[4][0], a45.x, b.x);  FMA2(acc[4][1], a45.x, b.y);
            FMA2(acc[5][0], a45.y, b.x);  FMA2(acc[5][1], a45.y, b.y);
            FMA2(acc[6][0], a67.x, b.x);  FMA2(acc[6][1], a67.x, b.y);
            FMA2(acc[7][0], a67.y, b.x);  FMA2(acc[7][1], a67.y, b.y);
        }
        __syncthreads();
    }

    float4 bb = *(const float4*)(bias + tcol * 4);
    #pragma unroll
    for (int r = 0; r < 8; r++) {
        int row = row0 + trow * 8 + r;
        if (row < n) {
            float2 lo, hi;
            lo = *(const float2*)&acc[r][0];
            hi = *(const float2*)&acc[r][1];
            float4 o;
            o.x = lo.x + bb.x;  o.y = lo.y + bb.y;
            o.z = hi.x + bb.z;  o.w = hi.y + bb.w;
            *(float4*)&g_H[(long)row * COUT_ + tcol * 4] = o;
        }
    }
}

// ---------------------------------------------------------------------------
// 7) gather: out[d] = relu( sum_e dinv[s]*dinv[d]*H[s]  +  H[d]*dinv[d]^2 )
//    16 threads per node (one float4 each), unroll-4 for MLP
// ---------------------------------------------------------------------------
__global__ __launch_bounds__(256) void gather_kernel(float* __restrict__ out, int n) {
    long t = (long)blockIdx.x * blockDim.x + threadIdx.x;
    int node = (int)(t >> 4);
    if (node >= n) return;
    int c = ((int)t & 15) * 4;

    float dd  = g_dinv[node];
    long  off = (long)node * COUT_ + c;

    float4 h  = *(const float4*)&g_H[off];
    float self = dd * dd;
    float4 acc;
    acc.x = h.x * self;  acc.y = h.y * self;
    acc.z = h.z * self;  acc.w = h.w * self;

    const int2* ep = &g_edge[g_rowoff[node]];
    int m = g_deg[node];

    int j = 0;
    for (; j + 4 <= m; j += 4) {
        int2 e0 = ep[j], e1 = ep[j + 1], e2 = ep[j + 2], e3 = ep[j + 3];
        float4 h0 = *(const float4*)&g_H[(long)e0.x * COUT_ + c];
        float4 h1 = *(const float4*)&g_H[(long)e1.x * COUT_ + c];
        float4 h2 = *(const float4*)&g_H[(long)e2.x * COUT_ + c];
        float4 h3 = *(const float4*)&g_H[(long)e3.x * COUT_ + c];
        float c0 = __int_as_float(e0.y) * dd;
        float c1 = __int_as_float(e1.y) * dd;
        float c2 = __int_as_float(e2.y) * dd;
        float c3 = __int_as_float(e3.y) * dd;
        acc.x = fmaf(h0.x, c0, acc.x); acc.y = fmaf(h0.y, c0, acc.y);
        acc.z = fmaf(h0.z, c0, acc.z); acc.w = fmaf(h0.w, c0, acc.w);
        acc.x = fmaf(h1.x, c1, acc.x); acc.y = fmaf(h1.y, c1, acc.y);
        acc.z = fmaf(h1.z, c1, acc.z); acc.w = fmaf(h1.w, c1, acc.w);
        acc.x = fmaf(h2.x, c2, acc.x); acc.y = fmaf(h2.y, c2, acc.y);
        acc.z = fmaf(h2.z, c2, acc.z); acc.w = fmaf(h2.w, c2, acc.w);
        acc.x = fmaf(h3.x, c3, acc.x); acc.y = fmaf(h3.y, c3, acc.y);
        acc.z = fmaf(h3.z, c3, acc.z); acc.w = fmaf(h3.w, c3, acc.w);
    }
    for (; j < m; j++) {
        int2 e = ep[j];
        float co = __int_as_float(e.y) * dd;
        float4 hh = *(const float4*)&g_H[(long)e.x * COUT_ + c];
        acc.x = fmaf(hh.x, co, acc.x); acc.y = fmaf(hh.y, co, acc.y);
        acc.z = fmaf(hh.z, co, acc.z); acc.w = fmaf(hh.w, co, acc.w);
    }

    float4 o;
    o.x = fmaxf(acc.x, 0.0f); o.y = fmaxf(acc.y, 0.0f);
    o.z = fmaxf(acc.z, 0.0f); o.w = fmaxf(acc.w, 0.0f);
    *(float4*)&out[off] = o;
}

// ---------------------------------------------------------------------------
extern "C" void kernel_launch(void* const* d_in, const int* in_sizes, int n_in,
                              void* d_out, int out_size)
{
    const float* X    = (const float*)d_in[0];   // (N, 128)
    const float* W    = (const float*)d_in[1];   // (128, 64)
    const float* bias = (const float*)d_in[2];   // (64,)
    const int*   src  = (const int*)d_in[3];     // (E,)
    const int*   dst  = (const int*)d_in[4];     // (E,)
    float*       out  = (float*)d_out;           // (N, 64)

    const int n = in_sizes[0] / CIN_;
    const int E = in_sizes[3];
    const int nblk = (n + SCAN_C - 1) / SCAN_C;

    zero_kernel<<<(n + 255) / 256, 256>>>(n);
    deg_kernel<<<(E + 255) / 256, 256>>>(dst, E);
    scan1_kernel<<<nblk, 256>>>(n);
    scan2_kernel<<<1, 128>>>(nblk);
    scan3_kernel<<<(n + 255) / 256, 256>>>(n);
    fill_kernel<<<(E + 255) / 256, 256>>>(src, dst, E);
    gemm_kernel<<<(n + 127) / 128, 256>>>(X, W, bias, n);
    {
        long threads = (long)n * 16;
        int blocks = (int)((threads + 255) / 256);
        gather_kernel<<<blocks, 256>>>(out, n);
    }
}